// round 6
// baseline (speedup 1.0000x reference)
#include <cuda_runtime.h>
#include <cuda_bf16.h>
#include <cstdint>

// Problem constants (fixed by the dataset)
#define NN_MAX   50000
#define EDGE_MAX 800000
#define IN_CH    256
#define C1       128
#define C2       64

// -------- scratch (no allocations allowed -> __device__ globals) -----------
__device__ int   g_deg     [NN_MAX];
__device__ int   g_prefix  [NN_MAX];
__device__ int   g_bsum    [256];
__device__ int   g_rowstart[NN_MAX];
__device__ int   g_cursor  [NN_MAX];
__device__ int   g_csr     [EDGE_MAX];
__device__ float g_dis     [NN_MAX];
__device__ float g_hs1     [NN_MAX * C1];
__device__ float g_x2      [NN_MAX * C1];
__device__ float g_hs2     [NN_MAX * C2];
// Pre-swizzled (SW128) bf16 hi/lo images of W^T, layout [kchunk][n][k64], 128B rows.
__device__ uint4 g_W1hi[4096], g_W1lo[4096];   // 4 chunks x 128n x 128B
__device__ uint4 g_W2hi[1024], g_W2lo[1024];   // 2 chunks x  64n x 128B

#define SW128(o) ((o) ^ (((o) >> 3) & 0x70))

__device__ __forceinline__ uint32_t smem_u32(const void* p) {
    uint32_t a;
    asm("{ .reg .u64 t; cvta.to.shared.u64 t, %1; cvt.u32.u64 %0, t; }" : "=r"(a) : "l"(p));
    return a;
}
__device__ __forceinline__ void ldsm_x4(uint32_t* r, uint32_t addr) {
    asm volatile("ldmatrix.sync.aligned.m8n8.x4.shared.b16 {%0,%1,%2,%3}, [%4];"
                 : "=r"(r[0]), "=r"(r[1]), "=r"(r[2]), "=r"(r[3]) : "r"(addr));
}
__device__ __forceinline__ void mma_bf16(float* d, const uint32_t* a,
                                         uint32_t b0, uint32_t b1) {
    asm volatile(
        "mma.sync.aligned.m16n8k16.row.col.f32.bf16.bf16.f32 "
        "{%0,%1,%2,%3}, {%4,%5,%6,%7}, {%8,%9}, {%0,%1,%2,%3};"
        : "+f"(d[0]), "+f"(d[1]), "+f"(d[2]), "+f"(d[3])
        : "r"(a[0]), "r"(a[1]), "r"(a[2]), "r"(a[3]), "r"(b0), "r"(b1));
}

// ---------------------------------------------------------------------------
// Fused prep: zero g_deg + build swizzled bf16 hi/lo weight images.
__global__ void prep_kernel(const float* __restrict__ W1, const float* __restrict__ W2, int n) {
    int idx = blockIdx.x * blockDim.x + threadIdx.x;
    if (idx < n) g_deg[idx] = 0;
    if (idx < IN_CH * C1) {
        int k = idx / C1, nn = idx % C1;
        float v = W1[k * C1 + nn];
        __nv_bfloat16 h = __float2bfloat16_rn(v);
        __nv_bfloat16 l = __float2bfloat16_rn(v - __bfloat162float(h));
        int c = k >> 6, kk = k & 63;
        int off = c * 16384 + SW128(nn * 128 + kk * 2);
        *(__nv_bfloat16*)((char*)g_W1hi + off) = h;
        *(__nv_bfloat16*)((char*)g_W1lo + off) = l;
        if (idx < C1 * C2) {
            int k2 = idx / C2, n2 = idx % C2;
            float v2 = W2[k2 * C2 + n2];
            __nv_bfloat16 h2 = __float2bfloat16_rn(v2);
            __nv_bfloat16 l2 = __float2bfloat16_rn(v2 - __bfloat162float(h2));
            int c2 = k2 >> 6, kk2 = k2 & 63;
            int off2 = c2 * 8192 + SW128(n2 * 128 + kk2 * 2);
            *(__nv_bfloat16*)((char*)g_W2hi + off2) = h2;
            *(__nv_bfloat16*)((char*)g_W2lo + off2) = l2;
        }
    }
}

// Degree count: 4 edges per thread (int4 load) for MLP.
__global__ void deg_kernel(const int* __restrict__ dst, int E) {
    int base = (blockIdx.x * blockDim.x + threadIdx.x) * 4;
    if (base + 3 < E) {
        int4 d = *(const int4*)&dst[base];
        atomicAdd(&g_deg[d.x], 1);
        atomicAdd(&g_deg[d.y], 1);
        atomicAdd(&g_deg[d.z], 1);
        atomicAdd(&g_deg[d.w], 1);
    } else {
        for (int e = base; e < E; e++) atomicAdd(&g_deg[dst[e]], 1);
    }
}

// Parallel scan phase A: per-block exclusive prefix + block sums.
__global__ __launch_bounds__(512) void scanA(int n) {
    __shared__ int s[512];
    int t = threadIdx.x;
    int i = blockIdx.x * 512 + t;
    int v = (i < n) ? g_deg[i] : 0;
    s[t] = v; __syncthreads();
    for (int off = 1; off < 512; off <<= 1) {
        int u = (t >= off) ? s[t - off] : 0;
        __syncthreads(); s[t] += u; __syncthreads();
    }
    if (i < n) g_prefix[i] = s[t] - v;
    if (t == 511) g_bsum[blockIdx.x] = s[511];
}
// Phase B+C fused: every block redundantly scans the <=256 block sums in smem.
__global__ __launch_bounds__(256) void scanC(int n, int nb) {
    __shared__ int sb_[256];
    int t = threadIdx.x;
    int v = (t < nb) ? g_bsum[t] : 0;
    sb_[t] = v; __syncthreads();
    for (int off = 1; off < 256; off <<= 1) {
        int u = (t >= off) ? sb_[t - off] : 0;
        __syncthreads(); sb_[t] += u; __syncthreads();
    }
    // sb_[j] is inclusive; exclusive = sb_[j] - bsum[j]; store exclusive in place
    if (t < nb) sb_[t] -= v;
    __syncthreads();
    int i = blockIdx.x * 256 + t;
    if (i >= n) return;
    int base = sb_[i >> 9] + g_prefix[i];
    g_rowstart[i] = base;
    g_cursor[i]   = base;
    g_dis[i]      = rsqrtf((float)g_deg[i] + 1.0f);
}

// CSR fill: 4 edges per thread for MLP on the ATOMG->STG chains.
__global__ void fill_csr(const int* __restrict__ src, const int* __restrict__ dst, int E) {
    int base = (blockIdx.x * blockDim.x + threadIdx.x) * 4;
    if (base + 3 < E) {
        int4 d = *(const int4*)&dst[base];
        int4 s = *(const int4*)&src[base];
        int p0 = atomicAdd(&g_cursor[d.x], 1);
        int p1 = atomicAdd(&g_cursor[d.y], 1);
        int p2 = atomicAdd(&g_cursor[d.z], 1);
        int p3 = atomicAdd(&g_cursor[d.w], 1);
        g_csr[p0] = s.x;
        g_csr[p1] = s.y;
        g_csr[p2] = s.z;
        g_csr[p3] = s.w;
    } else {
        for (int e = base; e < E; e++) {
            int p = atomicAdd(&g_cursor[dst[e]], 1);
            g_csr[p] = src[e];
        }
    }
}

// ---------------------------------------------------------------------------
// Warp-MMA split-bf16 GEMM: C[m][n] = dis[m] * sum_k A[m][k] * W[k][n]
template<int MTILE, int NDIM, int KDIM, int WM, int WN>
__global__ __launch_bounds__(256) void gemm_mma(
    const float* __restrict__ A, const uint4* __restrict__ Bhi,
    const uint4* __restrict__ Blo, float* __restrict__ Cout, int M)
{
    constexpr int SA_HI = 0;
    constexpr int SA_LO = MTILE * 128;
    constexpr int SB_HI = 2 * MTILE * 128;
    constexpr int SB_LO = SB_HI + NDIM * 128;
    constexpr int NCH   = KDIM / 64;
    constexpr int BNV   = NDIM * 8;

    extern __shared__ char smem[];
    const uint32_t sb = smem_u32(smem);
    const int tid  = threadIdx.x;
    const int wid  = tid >> 5, lane = tid & 31;
    const int wm   = wid / WN, wn = wid % WN;
    const int m0   = blockIdx.x * MTILE;

    const int row_l  = lane & 15;
    const int colsel = (lane >> 4) * 8;

    float acc[2][NDIM / 8][4];
#pragma unroll
    for (int i = 0; i < 2; i++)
#pragma unroll
        for (int j = 0; j < NDIM / 8; j++)
#pragma unroll
            for (int q = 0; q < 4; q++) acc[i][j][q] = 0.0f;

    for (int c = 0; c < NCH; c++) {
        for (int i = tid; i < MTILE * 16; i += 256) {
            int m = i >> 4, kk = (i & 15) * 4;
            int gm = m0 + m;
            float4 v = make_float4(0.f, 0.f, 0.f, 0.f);
            if (gm < M) v = *(const float4*)&A[(size_t)gm * KDIM + c * 64 + kk];
            __nv_bfloat16 h0 = __float2bfloat16_rn(v.x), h1 = __float2bfloat16_rn(v.y);
            __nv_bfloat16 h2 = __float2bfloat16_rn(v.z), h3 = __float2bfloat16_rn(v.w);
            __nv_bfloat16 l0 = __float2bfloat16_rn(v.x - __bfloat162float(h0));
            __nv_bfloat16 l1 = __float2bfloat16_rn(v.y - __bfloat162float(h1));
            __nv_bfloat16 l2 = __float2bfloat16_rn(v.z - __bfloat162float(h2));
            __nv_bfloat16 l3 = __float2bfloat16_rn(v.w - __bfloat162float(h3));
            uint32_t hA = ((uint32_t)__bfloat16_as_ushort(h1) << 16) | __bfloat16_as_ushort(h0);
            uint32_t hB = ((uint32_t)__bfloat16_as_ushort(h3) << 16) | __bfloat16_as_ushort(h2);
            uint32_t lA = ((uint32_t)__bfloat16_as_ushort(l1) << 16) | __bfloat16_as_ushort(l0);
            uint32_t lB = ((uint32_t)__bfloat16_as_ushort(l3) << 16) | __bfloat16_as_ushort(l2);
            int off = SW128(m * 128 + kk * 2);
            *(uint2*)(smem + SA_HI + off) = make_uint2(hA, hB);
            *(uint2*)(smem + SA_LO + off) = make_uint2(lA, lB);
        }
        {
            uint4* bh = (uint4*)(smem + SB_HI);
            uint4* bl = (uint4*)(smem + SB_LO);
            const uint4* gh = Bhi + (size_t)c * BNV;
            const uint4* gl = Blo + (size_t)c * BNV;
            for (int i = tid; i < BNV; i += 256) { bh[i] = gh[i]; bl[i] = gl[i]; }
        }
        __syncthreads();

#pragma unroll
        for (int k16 = 0; k16 < 4; k16++) {
            const int kb = k16 * 16;
            uint32_t ah[2][4], al[2][4];
#pragma unroll
            for (int im = 0; im < 2; im++) {
                int aoff = SW128((wm * 32 + im * 16 + row_l) * 128 + (kb + colsel) * 2);
                ldsm_x4(ah[im], sb + SA_HI + aoff);
                ldsm_x4(al[im], sb + SA_LO + aoff);
            }
#pragma unroll
            for (int j2 = 0; j2 < NDIM / (WN * 16); j2++) {
                int boff = SW128((wn * 64 + j2 * 16 + row_l) * 128 + (kb + colsel) * 2);
                uint32_t bh[4], bl[4];
                ldsm_x4(bh, sb + SB_HI + boff);
                ldsm_x4(bl, sb + SB_LO + boff);
#pragma unroll
                for (int im = 0; im < 2; im++) {
                    float* d0 = acc[im][2 * j2];
                    float* d1 = acc[im][2 * j2 + 1];
                    mma_bf16(d0, ah[im], bh[0], bh[2]);
                    mma_bf16(d0, ah[im], bl[0], bl[2]);
                    mma_bf16(d0, al[im], bh[0], bh[2]);
                    mma_bf16(d1, ah[im], bh[1], bh[3]);
                    mma_bf16(d1, ah[im], bl[1], bl[3]);
                    mma_bf16(d1, al[im], bh[1], bh[3]);
                }
            }
        }
        __syncthreads();
    }

#pragma unroll
    for (int im = 0; im < 2; im++) {
        int row0 = m0 + wm * 32 + im * 16 + (lane >> 2);
        int row1 = row0 + 8;
        float d0 = (row0 < M) ? g_dis[row0] : 0.0f;
        float d1 = (row1 < M) ? g_dis[row1] : 0.0f;
#pragma unroll
        for (int j = 0; j < NDIM / (WN * 8); j++) {
            int col = wn * 64 + j * 8 + (lane & 3) * 2;
            if (row0 < M)
                *(float2*)&Cout[(size_t)row0 * NDIM + col] =
                    make_float2(acc[im][j][0] * d0, acc[im][j][1] * d0);
            if (row1 < M)
                *(float2*)&Cout[(size_t)row1 * NDIM + col] =
                    make_float2(acc[im][j][2] * d1, acc[im][j][3] * d1);
        }
    }
}

// ---------------------------------------------------------------------------
// Gather-reduce aggregation, 128 channels: one warp per dst node, 8-deep unroll.
__global__ __launch_bounds__(256)
void agg128(const float* __restrict__ hs, const float* __restrict__ bias,
            float* __restrict__ out, int n) {
    int warp = (blockIdx.x * blockDim.x + threadIdx.x) >> 5;
    int lane = threadIdx.x & 31;
    if (warp >= n) return;
    const int node = warp;

    float4 acc = *(const float4*)&hs[(size_t)node * C1 + lane * 4];
    int e   = g_rowstart[node];
    int cnt = g_deg[node];

    while (cnt > 0) {
        int take = min(cnt, 32);
        int s = 0;
        if (lane < take) s = g_csr[e + lane];
        int k = 0;
        for (; k + 8 <= take; k += 8) {
            float4 v[8];
#pragma unroll
            for (int q = 0; q < 8; q++) {
                int sq = __shfl_sync(0xffffffffu, s, k + q);
                v[q] = *(const float4*)&hs[(size_t)sq * C1 + lane * 4];
            }
            float4 p0, p1;
            p0.x = (v[0].x + v[1].x) + (v[2].x + v[3].x);
            p0.y = (v[0].y + v[1].y) + (v[2].y + v[3].y);
            p0.z = (v[0].z + v[1].z) + (v[2].z + v[3].z);
            p0.w = (v[0].w + v[1].w) + (v[2].w + v[3].w);
            p1.x = (v[4].x + v[5].x) + (v[6].x + v[7].x);
            p1.y = (v[4].y + v[5].y) + (v[6].y + v[7].y);
            p1.z = (v[4].z + v[5].z) + (v[6].z + v[7].z);
            p1.w = (v[4].w + v[5].w) + (v[6].w + v[7].w);
            acc.x += p0.x + p1.x;
            acc.y += p0.y + p1.y;
            acc.z += p0.z + p1.z;
            acc.w += p0.w + p1.w;
        }
        for (; k < take; k++) {
            int sk = __shfl_sync(0xffffffffu, s, k);
            float4 v = *(const float4*)&hs[(size_t)sk * C1 + lane * 4];
            acc.x += v.x; acc.y += v.y; acc.z += v.z; acc.w += v.w;
        }
        e += take; cnt -= take;
    }

    float d   = g_dis[node];
    float4 bb = ((const float4*)bias)[lane];
    float4 r;
    r.x = fmaxf(fmaf(d, acc.x, bb.x), 0.0f);
    r.y = fmaxf(fmaf(d, acc.y, bb.y), 0.0f);
    r.z = fmaxf(fmaf(d, acc.z, bb.z), 0.0f);
    r.w = fmaxf(fmaf(d, acc.w, bb.w), 0.0f);
    *(float4*)&out[(size_t)node * C1 + lane * 4] = r;
}

// 64-channel aggregation: TWO nodes per warp, 16 lanes x float4 each.
__global__ __launch_bounds__(256)
void agg64(const float* __restrict__ hs, const float* __restrict__ bias,
           float* __restrict__ out, int n) {
    int warp  = (blockIdx.x * blockDim.x + threadIdx.x) >> 5;
    int lane  = threadIdx.x & 31;
    int group = lane >> 4;        // 0 or 1
    int gl    = lane & 15;        // lane within group
    int node  = warp * 2 + group;
    if (warp * 2 >= n) return;
    int node_eff = min(node, n - 1);
    const int gbase = group << 4;

    float4 acc = *(const float4*)&hs[(size_t)node_eff * C2 + gl * 4];
    int e   = g_rowstart[node_eff];
    int cnt = g_deg[node_eff];

    while (cnt > 0) {
        int take = min(cnt, 16);
        int s = 0;
        if (gl < take) s = g_csr[e + gl];
        int k = 0;
        for (; k + 4 <= take; k += 4) {
            int s0 = __shfl_sync(0xffffffffu, s, gbase + k + 0);
            int s1 = __shfl_sync(0xffffffffu, s, gbase + k + 1);
            int s2 = __shfl_sync(0xffffffffu, s, gbase + k + 2);
            int s3 = __shfl_sync(0xffffffffu, s, gbase + k + 3);
            float4 v0 = *(const float4*)&hs[(size_t)s0 * C2 + gl * 4];
            float4 v1 = *(const float4*)&hs[(size_t)s1 * C2 + gl * 4];
            float4 v2 = *(const float4*)&hs[(size_t)s2 * C2 + gl * 4];
            float4 v3 = *(const float4*)&hs[(size_t)s3 * C2 + gl * 4];
            acc.x += (v0.x + v1.x) + (v2.x + v3.x);
            acc.y += (v0.y + v1.y) + (v2.y + v3.y);
            acc.z += (v0.z + v1.z) + (v2.z + v3.z);
            acc.w += (v0.w + v1.w) + (v2.w + v3.w);
        }
        for (; k < take; k++) {
            int sk = __shfl_sync(0xffffffffu, s, gbase + k);
            float4 v = *(const float4*)&hs[(size_t)sk * C2 + gl * 4];
            acc.x += v.x; acc.y += v.y; acc.z += v.z; acc.w += v.w;
        }
        e += take; cnt -= take;
    }

    if (node < n) {
        float d   = g_dis[node];
        float4 bb = ((const float4*)bias)[gl];
        float4 r;
        r.x = fmaxf(fmaf(d, acc.x, bb.x), 0.0f);
        r.y = fmaxf(fmaf(d, acc.y, bb.y), 0.0f);
        r.z = fmaxf(fmaf(d, acc.z, bb.z), 0.0f);
        r.w = fmaxf(fmaf(d, acc.w, bb.w), 0.0f);
        *(float4*)&out[(size_t)node * C2 + gl * 4] = r;
    }
}

// ---------------------------------------------------------------------------
extern "C" void kernel_launch(void* const* d_in, const int* in_sizes, int n_in,
                              void* d_out, int out_size) {
    const float* x  = (const float*)d_in[0];
    const int*   ei = (const int*)d_in[1];
    const float* W1 = (const float*)d_in[2];
    const float* b1 = (const float*)d_in[3];
    const float* W2 = (const float*)d_in[4];
    const float* b2 = (const float*)d_in[5];
    float* out = (float*)d_out;

    const int E = in_sizes[1] / 2;
    const int N = in_sizes[0] / IN_CH;
    const int* src = ei;
    const int* dst = ei + E;

    float *hs1, *x2, *hs2;
    uint4 *w1h, *w1l, *w2h, *w2l;
    cudaGetSymbolAddress((void**)&hs1, g_hs1);
    cudaGetSymbolAddress((void**)&x2,  g_x2);
    cudaGetSymbolAddress((void**)&hs2, g_hs2);
    cudaGetSymbolAddress((void**)&w1h, g_W1hi);
    cudaGetSymbolAddress((void**)&w1l, g_W1lo);
    cudaGetSymbolAddress((void**)&w2h, g_W2hi);
    cudaGetSymbolAddress((void**)&w2l, g_W2lo);

    constexpr int SMEM1 = 2 * 128 * 128 + 2 * 128 * 128;  // 65536
    constexpr int SMEM2 = 2 * 256 * 128 + 2 * 64 * 128;   // 81920
    cudaFuncSetAttribute(gemm_mma<128, 128, 256, 4, 2>,
                         cudaFuncAttributeMaxDynamicSharedMemorySize, SMEM1);
    cudaFuncSetAttribute(gemm_mma<256, 64, 128, 8, 1>,
                         cudaFuncAttributeMaxDynamicSharedMemorySize, SMEM2);

    // prep: zero deg + weight images
    {
        int total = (N > IN_CH * C1) ? N : IN_CH * C1;
        prep_kernel<<<(total + 255) / 256, 256>>>(W1, W2, N);
    }
    deg_kernel<<<((E + 3) / 4 + 255) / 256, 256>>>(dst, E);
    int nb = (N + 511) / 512;
    scanA<<<nb, 512>>>(N);
    scanC<<<(N + 255) / 256, 256>>>(N, nb);
    fill_csr<<<((E + 3) / 4 + 255) / 256, 256>>>(src, dst, E);

    // ---- layer 1 ----
    gemm_mma<128, 128, 256, 4, 2><<<(N + 127) / 128, 256, SMEM1>>>(x, w1h, w1l, hs1, N);
    agg128<<<(N * 32 + 255) / 256, 256>>>(hs1, b1, x2, N);

    // ---- layer 2 ----
    gemm_mma<256, 64, 128, 8, 1><<<(N + 255) / 256, 256, SMEM2>>>(x2, w2h, w2l, hs2, N);
    agg64<<<((N + 1) / 2 * 32 + 255) / 256, 256>>>(hs2, b2, out, N);
}

// round 7
// speedup vs baseline: 1.0565x; 1.0565x over previous
#include <cuda_runtime.h>
#include <cuda_bf16.h>
#include <cstdint>

// Problem constants (fixed by the dataset)
#define NN_MAX   50000
#define EDGE_MAX 800000
#define IN_CH    256
#define C1       128
#define C2       64

// -------- scratch (no allocations allowed -> __device__ globals) -----------
__device__ int   g_deg     [NN_MAX];
__device__ int   g_prefix  [NN_MAX];
__device__ int   g_bsum    [256];
__device__ int   g_rowstart[NN_MAX];
__device__ int   g_cursor  [NN_MAX];
__device__ int   g_csr     [EDGE_MAX];
__device__ float g_dis     [NN_MAX];
__device__ float g_hs1     [NN_MAX * C1];
__device__ float g_x2      [NN_MAX * C1];
__device__ float g_hs2     [NN_MAX * C2];
// Pre-swizzled (SW128) bf16 hi/lo images of W^T, layout [kchunk][n][k64], 128B rows.
__device__ uint4 g_W1hi[4096], g_W1lo[4096];   // 4 chunks x 128n x 128B
__device__ uint4 g_W2hi[1024], g_W2lo[1024];   // 2 chunks x  64n x 128B

#define SW128(o) ((o) ^ (((o) >> 3) & 0x70))

__device__ __forceinline__ uint32_t smem_u32(const void* p) {
    uint32_t a;
    asm("{ .reg .u64 t; cvta.to.shared.u64 t, %1; cvt.u32.u64 %0, t; }" : "=r"(a) : "l"(p));
    return a;
}
__device__ __forceinline__ void ldsm_x4(uint32_t* r, uint32_t addr) {
    asm volatile("ldmatrix.sync.aligned.m8n8.x4.shared.b16 {%0,%1,%2,%3}, [%4];"
                 : "=r"(r[0]), "=r"(r[1]), "=r"(r[2]), "=r"(r[3]) : "r"(addr));
}
__device__ __forceinline__ void mma_bf16(float* d, const uint32_t* a,
                                         uint32_t b0, uint32_t b1) {
    asm volatile(
        "mma.sync.aligned.m16n8k16.row.col.f32.bf16.bf16.f32 "
        "{%0,%1,%2,%3}, {%4,%5,%6,%7}, {%8,%9}, {%0,%1,%2,%3};"
        : "+f"(d[0]), "+f"(d[1]), "+f"(d[2]), "+f"(d[3])
        : "r"(a[0]), "r"(a[1]), "r"(a[2]), "r"(a[3]), "r"(b0), "r"(b1));
}

// ---------------------------------------------------------------------------
// Fused prep: zero g_deg + build swizzled bf16 hi/lo weight images.
__global__ void prep_kernel(const float* __restrict__ W1, const float* __restrict__ W2, int n) {
    int idx = blockIdx.x * blockDim.x + threadIdx.x;
    if (idx < n) g_deg[idx] = 0;
    if (idx < IN_CH * C1) {
        int k = idx / C1, nn = idx % C1;
        float v = W1[k * C1 + nn];
        __nv_bfloat16 h = __float2bfloat16_rn(v);
        __nv_bfloat16 l = __float2bfloat16_rn(v - __bfloat162float(h));
        int c = k >> 6, kk = k & 63;
        int off = c * 16384 + SW128(nn * 128 + kk * 2);
        *(__nv_bfloat16*)((char*)g_W1hi + off) = h;
        *(__nv_bfloat16*)((char*)g_W1lo + off) = l;
        if (idx < C1 * C2) {
            int k2 = idx / C2, n2 = idx % C2;
            float v2 = W2[k2 * C2 + n2];
            __nv_bfloat16 h2 = __float2bfloat16_rn(v2);
            __nv_bfloat16 l2 = __float2bfloat16_rn(v2 - __bfloat162float(h2));
            int c2 = k2 >> 6, kk2 = k2 & 63;
            int off2 = c2 * 8192 + SW128(n2 * 128 + kk2 * 2);
            *(__nv_bfloat16*)((char*)g_W2hi + off2) = h2;
            *(__nv_bfloat16*)((char*)g_W2lo + off2) = l2;
        }
    }
}

// Degree count: 4 edges per thread (int4 load) for MLP.
__global__ void deg_kernel(const int* __restrict__ dst, int E) {
    int base = (blockIdx.x * blockDim.x + threadIdx.x) * 4;
    if (base + 3 < E) {
        int4 d = *(const int4*)&dst[base];
        atomicAdd(&g_deg[d.x], 1);
        atomicAdd(&g_deg[d.y], 1);
        atomicAdd(&g_deg[d.z], 1);
        atomicAdd(&g_deg[d.w], 1);
    } else {
        for (int e = base; e < E; e++) atomicAdd(&g_deg[dst[e]], 1);
    }
}

// Parallel scan phase A: per-block exclusive prefix + block sums.
__global__ __launch_bounds__(512) void scanA(int n) {
    __shared__ int s[512];
    int t = threadIdx.x;
    int i = blockIdx.x * 512 + t;
    int v = (i < n) ? g_deg[i] : 0;
    s[t] = v; __syncthreads();
    for (int off = 1; off < 512; off <<= 1) {
        int u = (t >= off) ? s[t - off] : 0;
        __syncthreads(); s[t] += u; __syncthreads();
    }
    if (i < n) g_prefix[i] = s[t] - v;
    if (t == 511) g_bsum[blockIdx.x] = s[511];
}
// Phase B+C fused: every block redundantly scans the <=256 block sums in smem.
__global__ __launch_bounds__(256) void scanC(int n, int nb) {
    __shared__ int sb_[256];
    int t = threadIdx.x;
    int v = (t < nb) ? g_bsum[t] : 0;
    sb_[t] = v; __syncthreads();
    for (int off = 1; off < 256; off <<= 1) {
        int u = (t >= off) ? sb_[t - off] : 0;
        __syncthreads(); sb_[t] += u; __syncthreads();
    }
    if (t < nb) sb_[t] -= v;
    __syncthreads();
    int i = blockIdx.x * 256 + t;
    if (i >= n) return;
    int base = sb_[i >> 9] + g_prefix[i];
    g_rowstart[i] = base;
    g_cursor[i]   = base;
    g_dis[i]      = rsqrtf((float)g_deg[i] + 1.0f);
}

// CSR fill: 4 edges per thread for MLP on the ATOMG->STG chains.
__global__ void fill_csr(const int* __restrict__ src, const int* __restrict__ dst, int E) {
    int base = (blockIdx.x * blockDim.x + threadIdx.x) * 4;
    if (base + 3 < E) {
        int4 d = *(const int4*)&dst[base];
        int4 s = *(const int4*)&src[base];
        int p0 = atomicAdd(&g_cursor[d.x], 1);
        int p1 = atomicAdd(&g_cursor[d.y], 1);
        int p2 = atomicAdd(&g_cursor[d.z], 1);
        int p3 = atomicAdd(&g_cursor[d.w], 1);
        g_csr[p0] = s.x;
        g_csr[p1] = s.y;
        g_csr[p2] = s.z;
        g_csr[p3] = s.w;
    } else {
        for (int e = base; e < E; e++) {
            int p = atomicAdd(&g_cursor[dst[e]], 1);
            g_csr[p] = src[e];
        }
    }
}

// ---------------------------------------------------------------------------
// Warp-MMA split-bf16 GEMM: C[m][n] = dis[m] * sum_k A[m][k] * W[k][n]
template<int MTILE, int NDIM, int KDIM, int WM, int WN>
__global__ __launch_bounds__(256) void gemm_mma(
    const float* __restrict__ A, const uint4* __restrict__ Bhi,
    const uint4* __restrict__ Blo, float* __restrict__ Cout, int M)
{
    constexpr int SA_HI = 0;
    constexpr int SA_LO = MTILE * 128;
    constexpr int SB_HI = 2 * MTILE * 128;
    constexpr int SB_LO = SB_HI + NDIM * 128;
    constexpr int NCH   = KDIM / 64;
    constexpr int BNV   = NDIM * 8;

    extern __shared__ char smem[];
    const uint32_t sb = smem_u32(smem);
    const int tid  = threadIdx.x;
    const int wid  = tid >> 5, lane = tid & 31;
    const int wm   = wid / WN, wn = wid % WN;
    const int m0   = blockIdx.x * MTILE;

    const int row_l  = lane & 15;
    const int colsel = (lane >> 4) * 8;

    float acc[2][NDIM / 8][4];
#pragma unroll
    for (int i = 0; i < 2; i++)
#pragma unroll
        for (int j = 0; j < NDIM / 8; j++)
#pragma unroll
            for (int q = 0; q < 4; q++) acc[i][j][q] = 0.0f;

    for (int c = 0; c < NCH; c++) {
        for (int i = tid; i < MTILE * 16; i += 256) {
            int m = i >> 4, kk = (i & 15) * 4;
            int gm = m0 + m;
            float4 v = make_float4(0.f, 0.f, 0.f, 0.f);
            if (gm < M) v = *(const float4*)&A[(size_t)gm * KDIM + c * 64 + kk];
            __nv_bfloat16 h0 = __float2bfloat16_rn(v.x), h1 = __float2bfloat16_rn(v.y);
            __nv_bfloat16 h2 = __float2bfloat16_rn(v.z), h3 = __float2bfloat16_rn(v.w);
            __nv_bfloat16 l0 = __float2bfloat16_rn(v.x - __bfloat162float(h0));
            __nv_bfloat16 l1 = __float2bfloat16_rn(v.y - __bfloat162float(h1));
            __nv_bfloat16 l2 = __float2bfloat16_rn(v.z - __bfloat162float(h2));
            __nv_bfloat16 l3 = __float2bfloat16_rn(v.w - __bfloat162float(h3));
            uint32_t hA = ((uint32_t)__bfloat16_as_ushort(h1) << 16) | __bfloat16_as_ushort(h0);
            uint32_t hB = ((uint32_t)__bfloat16_as_ushort(h3) << 16) | __bfloat16_as_ushort(h2);
            uint32_t lA = ((uint32_t)__bfloat16_as_ushort(l1) << 16) | __bfloat16_as_ushort(l0);
            uint32_t lB = ((uint32_t)__bfloat16_as_ushort(l3) << 16) | __bfloat16_as_ushort(l2);
            int off = SW128(m * 128 + kk * 2);
            *(uint2*)(smem + SA_HI + off) = make_uint2(hA, hB);
            *(uint2*)(smem + SA_LO + off) = make_uint2(lA, lB);
        }
        {
            uint4* bh = (uint4*)(smem + SB_HI);
            uint4* bl = (uint4*)(smem + SB_LO);
            const uint4* gh = Bhi + (size_t)c * BNV;
            const uint4* gl = Blo + (size_t)c * BNV;
            for (int i = tid; i < BNV; i += 256) { bh[i] = gh[i]; bl[i] = gl[i]; }
        }
        __syncthreads();

#pragma unroll
        for (int k16 = 0; k16 < 4; k16++) {
            const int kb = k16 * 16;
            uint32_t ah[2][4], al[2][4];
#pragma unroll
            for (int im = 0; im < 2; im++) {
                int aoff = SW128((wm * 32 + im * 16 + row_l) * 128 + (kb + colsel) * 2);
                ldsm_x4(ah[im], sb + SA_HI + aoff);
                ldsm_x4(al[im], sb + SA_LO + aoff);
            }
#pragma unroll
            for (int j2 = 0; j2 < NDIM / (WN * 16); j2++) {
                int boff = SW128((wn * 64 + j2 * 16 + row_l) * 128 + (kb + colsel) * 2);
                uint32_t bh[4], bl[4];
                ldsm_x4(bh, sb + SB_HI + boff);
                ldsm_x4(bl, sb + SB_LO + boff);
#pragma unroll
                for (int im = 0; im < 2; im++) {
                    float* d0 = acc[im][2 * j2];
                    float* d1 = acc[im][2 * j2 + 1];
                    mma_bf16(d0, ah[im], bh[0], bh[2]);
                    mma_bf16(d0, ah[im], bl[0], bl[2]);
                    mma_bf16(d0, al[im], bh[0], bh[2]);
                    mma_bf16(d1, ah[im], bh[1], bh[3]);
                    mma_bf16(d1, ah[im], bl[1], bl[3]);
                    mma_bf16(d1, al[im], bh[1], bh[3]);
                }
            }
        }
        __syncthreads();
    }

#pragma unroll
    for (int im = 0; im < 2; im++) {
        int row0 = m0 + wm * 32 + im * 16 + (lane >> 2);
        int row1 = row0 + 8;
        float d0 = (row0 < M) ? g_dis[row0] : 0.0f;
        float d1 = (row1 < M) ? g_dis[row1] : 0.0f;
#pragma unroll
        for (int j = 0; j < NDIM / (WN * 8); j++) {
            int col = wn * 64 + j * 8 + (lane & 3) * 2;
            if (row0 < M)
                *(float2*)&Cout[(size_t)row0 * NDIM + col] =
                    make_float2(acc[im][j][0] * d0, acc[im][j][1] * d0);
            if (row1 < M)
                *(float2*)&Cout[(size_t)row1 * NDIM + col] =
                    make_float2(acc[im][j][2] * d1, acc[im][j][3] * d1);
        }
    }
}

// ---------------------------------------------------------------------------
// Gather-reduce aggregation, 128 channels: one warp per dst node (4-deep unroll).
__global__ __launch_bounds__(256)
void agg128(const float* __restrict__ hs, const float* __restrict__ bias,
            float* __restrict__ out, int n) {
    int warp = (blockIdx.x * blockDim.x + threadIdx.x) >> 5;
    int lane = threadIdx.x & 31;
    if (warp >= n) return;
    const int node = warp;

    float4 acc = *(const float4*)&hs[(size_t)node * C1 + lane * 4];
    int e   = g_rowstart[node];
    int cnt = g_deg[node];

    while (cnt > 0) {
        int take = min(cnt, 32);
        int s = 0;
        if (lane < take) s = g_csr[e + lane];
        int k = 0;
        for (; k + 4 <= take; k += 4) {
            int s0 = __shfl_sync(0xffffffffu, s, k + 0);
            int s1 = __shfl_sync(0xffffffffu, s, k + 1);
            int s2 = __shfl_sync(0xffffffffu, s, k + 2);
            int s3 = __shfl_sync(0xffffffffu, s, k + 3);
            float4 v0 = *(const float4*)&hs[(size_t)s0 * C1 + lane * 4];
            float4 v1 = *(const float4*)&hs[(size_t)s1 * C1 + lane * 4];
            float4 v2 = *(const float4*)&hs[(size_t)s2 * C1 + lane * 4];
            float4 v3 = *(const float4*)&hs[(size_t)s3 * C1 + lane * 4];
            acc.x += (v0.x + v1.x) + (v2.x + v3.x);
            acc.y += (v0.y + v1.y) + (v2.y + v3.y);
            acc.z += (v0.z + v1.z) + (v2.z + v3.z);
            acc.w += (v0.w + v1.w) + (v2.w + v3.w);
        }
        for (; k < take; k++) {
            int sk = __shfl_sync(0xffffffffu, s, k);
            float4 v = *(const float4*)&hs[(size_t)sk * C1 + lane * 4];
            acc.x += v.x; acc.y += v.y; acc.z += v.z; acc.w += v.w;
        }
        e += take; cnt -= take;
    }

    float d   = g_dis[node];
    float4 bb = ((const float4*)bias)[lane];
    float4 r;
    r.x = fmaxf(fmaf(d, acc.x, bb.x), 0.0f);
    r.y = fmaxf(fmaf(d, acc.y, bb.y), 0.0f);
    r.z = fmaxf(fmaf(d, acc.z, bb.z), 0.0f);
    r.w = fmaxf(fmaf(d, acc.w, bb.w), 0.0f);
    *(float4*)&out[(size_t)node * C1 + lane * 4] = r;
}

// 64-channel aggregation: one warp per node, float2 lanes (convergent loop).
__global__ __launch_bounds__(256)
void agg64(const float* __restrict__ hs, const float* __restrict__ bias,
           float* __restrict__ out, int n) {
    int warp = (blockIdx.x * blockDim.x + threadIdx.x) >> 5;
    int lane = threadIdx.x & 31;
    if (warp >= n) return;
    const int node = warp;

    float2 acc = *(const float2*)&hs[(size_t)node * C2 + lane * 2];
    int e   = g_rowstart[node];
    int cnt = g_deg[node];

    while (cnt > 0) {
        int take = min(cnt, 32);
        int s = 0;
        if (lane < take) s = g_csr[e + lane];
        int k = 0;
        for (; k + 4 <= take; k += 4) {
            int s0 = __shfl_sync(0xffffffffu, s, k + 0);
            int s1 = __shfl_sync(0xffffffffu, s, k + 1);
            int s2 = __shfl_sync(0xffffffffu, s, k + 2);
            int s3 = __shfl_sync(0xffffffffu, s, k + 3);
            float2 v0 = *(const float2*)&hs[(size_t)s0 * C2 + lane * 2];
            float2 v1 = *(const float2*)&hs[(size_t)s1 * C2 + lane * 2];
            float2 v2 = *(const float2*)&hs[(size_t)s2 * C2 + lane * 2];
            float2 v3 = *(const float2*)&hs[(size_t)s3 * C2 + lane * 2];
            acc.x += (v0.x + v1.x) + (v2.x + v3.x);
            acc.y += (v0.y + v1.y) + (v2.y + v3.y);
        }
        for (; k < take; k++) {
            int sk = __shfl_sync(0xffffffffu, s, k);
            float2 v = *(const float2*)&hs[(size_t)sk * C2 + lane * 2];
            acc.x += v.x; acc.y += v.y;
        }
        e += take; cnt -= take;
    }

    float d   = g_dis[node];
    float2 bb = ((const float2*)bias)[lane];
    float2 r;
    r.x = fmaxf(fmaf(d, acc.x, bb.x), 0.0f);
    r.y = fmaxf(fmaf(d, acc.y, bb.y), 0.0f);
    *(float2*)&out[(size_t)node * C2 + lane * 2] = r;
}

// ---------------------------------------------------------------------------
extern "C" void kernel_launch(void* const* d_in, const int* in_sizes, int n_in,
                              void* d_out, int out_size) {
    const float* x  = (const float*)d_in[0];
    const int*   ei = (const int*)d_in[1];
    const float* W1 = (const float*)d_in[2];
    const float* b1 = (const float*)d_in[3];
    const float* W2 = (const float*)d_in[4];
    const float* b2 = (const float*)d_in[5];
    float* out = (float*)d_out;

    const int E = in_sizes[1] / 2;
    const int N = in_sizes[0] / IN_CH;
    const int* src = ei;
    const int* dst = ei + E;

    float *hs1, *x2, *hs2;
    uint4 *w1h, *w1l, *w2h, *w2l;
    cudaGetSymbolAddress((void**)&hs1, g_hs1);
    cudaGetSymbolAddress((void**)&x2,  g_x2);
    cudaGetSymbolAddress((void**)&hs2, g_hs2);
    cudaGetSymbolAddress((void**)&w1h, g_W1hi);
    cudaGetSymbolAddress((void**)&w1l, g_W1lo);
    cudaGetSymbolAddress((void**)&w2h, g_W2hi);
    cudaGetSymbolAddress((void**)&w2l, g_W2lo);

    constexpr int SMEM1 = 2 * 128 * 128 + 2 * 128 * 128;  // 65536
    constexpr int SMEM2 = 2 * 256 * 128 + 2 * 64 * 128;   // 81920
    cudaFuncSetAttribute(gemm_mma<128, 128, 256, 4, 2>,
                         cudaFuncAttributeMaxDynamicSharedMemorySize, SMEM1);
    cudaFuncSetAttribute(gemm_mma<256, 64, 128, 8, 1>,
                         cudaFuncAttributeMaxDynamicSharedMemorySize, SMEM2);

    // prep: zero deg + weight images
    {
        int total = (N > IN_CH * C1) ? N : IN_CH * C1;
        prep_kernel<<<(total + 255) / 256, 256>>>(W1, W2, N);
    }
    deg_kernel<<<((E + 3) / 4 + 255) / 256, 256>>>(dst, E);
    int nb = (N + 511) / 512;
    scanA<<<nb, 512>>>(N);
    scanC<<<(N + 255) / 256, 256>>>(N, nb);
    fill_csr<<<((E + 3) / 4 + 255) / 256, 256>>>(src, dst, E);

    // ---- layer 1 ----
    gemm_mma<128, 128, 256, 4, 2><<<(N + 127) / 128, 256, SMEM1>>>(x, w1h, w1l, hs1, N);
    agg128<<<(N * 32 + 255) / 256, 256>>>(hs1, b1, x2, N);

    // ---- layer 2 ----
    gemm_mma<256, 64, 128, 8, 1><<<(N + 255) / 256, 256, SMEM2>>>(x2, w2h, w2l, hs2, N);
    agg64<<<(N * 32 + 255) / 256, 256>>>(hs2, b2, out, N);
}

// round 8
// speedup vs baseline: 1.0792x; 1.0215x over previous
#include <cuda_runtime.h>
#include <cuda_bf16.h>
#include <cuda_fp16.h>
#include <cstdint>

// Problem constants (fixed by the dataset)
#define NN_MAX   50000
#define EDGE_MAX 800000
#define IN_CH    256
#define C1       128
#define C2       64

// -------- scratch (no allocations allowed -> __device__ globals) -----------
__device__ int    g_deg     [NN_MAX];
__device__ int    g_prefix  [NN_MAX];
__device__ int    g_bsum    [256];
__device__ int    g_rowstart[NN_MAX];
__device__ int    g_cursor  [NN_MAX];
__device__ int    g_csr     [EDGE_MAX];
__device__ float  g_dis     [NN_MAX];
__device__ __half g_hs1     [NN_MAX * C1];   // (x@W1)*dis, fp16
__device__ float  g_x2      [NN_MAX * C1];   // relu output of layer 1 (fp32)
__device__ __half g_hs2     [NN_MAX * C2];   // (x2@W2)*dis, fp16
// Pre-swizzled (SW128) bf16 hi/lo images of W^T, layout [kchunk][n][k64], 128B rows.
__device__ uint4 g_W1hi[4096], g_W1lo[4096];   // 4 chunks x 128n x 128B
__device__ uint4 g_W2hi[1024], g_W2lo[1024];   // 2 chunks x  64n x 128B

#define SW128(o) ((o) ^ (((o) >> 3) & 0x70))

__device__ __forceinline__ uint32_t smem_u32(const void* p) {
    uint32_t a;
    asm("{ .reg .u64 t; cvta.to.shared.u64 t, %1; cvt.u32.u64 %0, t; }" : "=r"(a) : "l"(p));
    return a;
}
__device__ __forceinline__ void ldsm_x4(uint32_t* r, uint32_t addr) {
    asm volatile("ldmatrix.sync.aligned.m8n8.x4.shared.b16 {%0,%1,%2,%3}, [%4];"
                 : "=r"(r[0]), "=r"(r[1]), "=r"(r[2]), "=r"(r[3]) : "r"(addr));
}
__device__ __forceinline__ void mma_bf16(float* d, const uint32_t* a,
                                         uint32_t b0, uint32_t b1) {
    asm volatile(
        "mma.sync.aligned.m16n8k16.row.col.f32.bf16.bf16.f32 "
        "{%0,%1,%2,%3}, {%4,%5,%6,%7}, {%8,%9}, {%0,%1,%2,%3};"
        : "+f"(d[0]), "+f"(d[1]), "+f"(d[2]), "+f"(d[3])
        : "r"(a[0]), "r"(a[1]), "r"(a[2]), "r"(a[3]), "r"(b0), "r"(b1));
}

// ---------------------------------------------------------------------------
// Fused prep: zero g_deg + build swizzled bf16 hi/lo weight images.
__global__ void prep_kernel(const float* __restrict__ W1, const float* __restrict__ W2, int n) {
    int idx = blockIdx.x * blockDim.x + threadIdx.x;
    if (idx < n) g_deg[idx] = 0;
    if (idx < IN_CH * C1) {
        int k = idx / C1, nn = idx % C1;
        float v = W1[k * C1 + nn];
        __nv_bfloat16 h = __float2bfloat16_rn(v);
        __nv_bfloat16 l = __float2bfloat16_rn(v - __bfloat162float(h));
        int c = k >> 6, kk = k & 63;
        int off = c * 16384 + SW128(nn * 128 + kk * 2);
        *(__nv_bfloat16*)((char*)g_W1hi + off) = h;
        *(__nv_bfloat16*)((char*)g_W1lo + off) = l;
        if (idx < C1 * C2) {
            int k2 = idx / C2, n2 = idx % C2;
            float v2 = W2[k2 * C2 + n2];
            __nv_bfloat16 h2 = __float2bfloat16_rn(v2);
            __nv_bfloat16 l2 = __float2bfloat16_rn(v2 - __bfloat162float(h2));
            int c2 = k2 >> 6, kk2 = k2 & 63;
            int off2 = c2 * 8192 + SW128(n2 * 128 + kk2 * 2);
            *(__nv_bfloat16*)((char*)g_W2hi + off2) = h2;
            *(__nv_bfloat16*)((char*)g_W2lo + off2) = l2;
        }
    }
}

// Degree count: 4 edges per thread (int4 load) for MLP.
__global__ void deg_kernel(const int* __restrict__ dst, int E) {
    int base = (blockIdx.x * blockDim.x + threadIdx.x) * 4;
    if (base + 3 < E) {
        int4 d = *(const int4*)&dst[base];
        atomicAdd(&g_deg[d.x], 1);
        atomicAdd(&g_deg[d.y], 1);
        atomicAdd(&g_deg[d.z], 1);
        atomicAdd(&g_deg[d.w], 1);
    } else {
        for (int e = base; e < E; e++) atomicAdd(&g_deg[dst[e]], 1);
    }
}

// Parallel scan phase A: per-block exclusive prefix + block sums.
__global__ __launch_bounds__(512) void scanA(int n) {
    __shared__ int s[512];
    int t = threadIdx.x;
    int i = blockIdx.x * 512 + t;
    int v = (i < n) ? g_deg[i] : 0;
    s[t] = v; __syncthreads();
    for (int off = 1; off < 512; off <<= 1) {
        int u = (t >= off) ? s[t - off] : 0;
        __syncthreads(); s[t] += u; __syncthreads();
    }
    if (i < n) g_prefix[i] = s[t] - v;
    if (t == 511) g_bsum[blockIdx.x] = s[511];
}
// Phase B+C fused: every block redundantly scans the <=256 block sums in smem.
__global__ __launch_bounds__(256) void scanC(int n, int nb) {
    __shared__ int sb_[256];
    int t = threadIdx.x;
    int v = (t < nb) ? g_bsum[t] : 0;
    sb_[t] = v; __syncthreads();
    for (int off = 1; off < 256; off <<= 1) {
        int u = (t >= off) ? sb_[t - off] : 0;
        __syncthreads(); sb_[t] += u; __syncthreads();
    }
    if (t < nb) sb_[t] -= v;
    __syncthreads();
    int i = blockIdx.x * 256 + t;
    if (i >= n) return;
    int base = sb_[i >> 9] + g_prefix[i];
    g_rowstart[i] = base;
    g_cursor[i]   = base;
    g_dis[i]      = rsqrtf((float)g_deg[i] + 1.0f);
}

// CSR fill: 4 edges per thread for MLP on the ATOMG->STG chains.
__global__ void fill_csr(const int* __restrict__ src, const int* __restrict__ dst, int E) {
    int base = (blockIdx.x * blockDim.x + threadIdx.x) * 4;
    if (base + 3 < E) {
        int4 d = *(const int4*)&dst[base];
        int4 s = *(const int4*)&src[base];
        int p0 = atomicAdd(&g_cursor[d.x], 1);
        int p1 = atomicAdd(&g_cursor[d.y], 1);
        int p2 = atomicAdd(&g_cursor[d.z], 1);
        int p3 = atomicAdd(&g_cursor[d.w], 1);
        g_csr[p0] = s.x;
        g_csr[p1] = s.y;
        g_csr[p2] = s.z;
        g_csr[p3] = s.w;
    } else {
        for (int e = base; e < E; e++) {
            int p = atomicAdd(&g_cursor[dst[e]], 1);
            g_csr[p] = src[e];
        }
    }
}

// ---------------------------------------------------------------------------
// Warp-MMA split-bf16 GEMM: hs[m][n] = half( dis[m] * sum_k A[m][k] * W[k][n] )
template<int MTILE, int NDIM, int KDIM, int WM, int WN>
__global__ __launch_bounds__(256) void gemm_mma(
    const float* __restrict__ A, const uint4* __restrict__ Bhi,
    const uint4* __restrict__ Blo, __half* __restrict__ Cout, int M)
{
    constexpr int SA_HI = 0;
    constexpr int SA_LO = MTILE * 128;
    constexpr int SB_HI = 2 * MTILE * 128;
    constexpr int SB_LO = SB_HI + NDIM * 128;
    constexpr int NCH   = KDIM / 64;
    constexpr int BNV   = NDIM * 8;

    extern __shared__ char smem[];
    const uint32_t sb = smem_u32(smem);
    const int tid  = threadIdx.x;
    const int wid  = tid >> 5, lane = tid & 31;
    const int wm   = wid / WN, wn = wid % WN;
    const int m0   = blockIdx.x * MTILE;

    const int row_l  = lane & 15;
    const int colsel = (lane >> 4) * 8;

    float acc[2][NDIM / 8][4];
#pragma unroll
    for (int i = 0; i < 2; i++)
#pragma unroll
        for (int j = 0; j < NDIM / 8; j++)
#pragma unroll
            for (int q = 0; q < 4; q++) acc[i][j][q] = 0.0f;

    for (int c = 0; c < NCH; c++) {
        for (int i = tid; i < MTILE * 16; i += 256) {
            int m = i >> 4, kk = (i & 15) * 4;
            int gm = m0 + m;
            float4 v = make_float4(0.f, 0.f, 0.f, 0.f);
            if (gm < M) v = *(const float4*)&A[(size_t)gm * KDIM + c * 64 + kk];
            __nv_bfloat16 h0 = __float2bfloat16_rn(v.x), h1 = __float2bfloat16_rn(v.y);
            __nv_bfloat16 h2 = __float2bfloat16_rn(v.z), h3 = __float2bfloat16_rn(v.w);
            __nv_bfloat16 l0 = __float2bfloat16_rn(v.x - __bfloat162float(h0));
            __nv_bfloat16 l1 = __float2bfloat16_rn(v.y - __bfloat162float(h1));
            __nv_bfloat16 l2 = __float2bfloat16_rn(v.z - __bfloat162float(h2));
            __nv_bfloat16 l3 = __float2bfloat16_rn(v.w - __bfloat162float(h3));
            uint32_t hA = ((uint32_t)__bfloat16_as_ushort(h1) << 16) | __bfloat16_as_ushort(h0);
            uint32_t hB = ((uint32_t)__bfloat16_as_ushort(h3) << 16) | __bfloat16_as_ushort(h2);
            uint32_t lA = ((uint32_t)__bfloat16_as_ushort(l1) << 16) | __bfloat16_as_ushort(l0);
            uint32_t lB = ((uint32_t)__bfloat16_as_ushort(l3) << 16) | __bfloat16_as_ushort(l2);
            int off = SW128(m * 128 + kk * 2);
            *(uint2*)(smem + SA_HI + off) = make_uint2(hA, hB);
            *(uint2*)(smem + SA_LO + off) = make_uint2(lA, lB);
        }
        {
            uint4* bh = (uint4*)(smem + SB_HI);
            uint4* bl = (uint4*)(smem + SB_LO);
            const uint4* gh = Bhi + (size_t)c * BNV;
            const uint4* gl = Blo + (size_t)c * BNV;
            for (int i = tid; i < BNV; i += 256) { bh[i] = gh[i]; bl[i] = gl[i]; }
        }
        __syncthreads();

#pragma unroll
        for (int k16 = 0; k16 < 4; k16++) {
            const int kb = k16 * 16;
            uint32_t ah[2][4], al[2][4];
#pragma unroll
            for (int im = 0; im < 2; im++) {
                int aoff = SW128((wm * 32 + im * 16 + row_l) * 128 + (kb + colsel) * 2);
                ldsm_x4(ah[im], sb + SA_HI + aoff);
                ldsm_x4(al[im], sb + SA_LO + aoff);
            }
#pragma unroll
            for (int j2 = 0; j2 < NDIM / (WN * 16); j2++) {
                int boff = SW128((wn * 64 + j2 * 16 + row_l) * 128 + (kb + colsel) * 2);
                uint32_t bh[4], bl[4];
                ldsm_x4(bh, sb + SB_HI + boff);
                ldsm_x4(bl, sb + SB_LO + boff);
#pragma unroll
                for (int im = 0; im < 2; im++) {
                    float* d0 = acc[im][2 * j2];
                    float* d1 = acc[im][2 * j2 + 1];
                    mma_bf16(d0, ah[im], bh[0], bh[2]);
                    mma_bf16(d0, ah[im], bl[0], bl[2]);
                    mma_bf16(d0, al[im], bh[0], bh[2]);
                    mma_bf16(d1, ah[im], bh[1], bh[3]);
                    mma_bf16(d1, ah[im], bl[1], bl[3]);
                    mma_bf16(d1, al[im], bh[1], bh[3]);
                }
            }
        }
        __syncthreads();
    }

#pragma unroll
    for (int im = 0; im < 2; im++) {
        int row0 = m0 + wm * 32 + im * 16 + (lane >> 2);
        int row1 = row0 + 8;
        float d0 = (row0 < M) ? g_dis[row0] : 0.0f;
        float d1 = (row1 < M) ? g_dis[row1] : 0.0f;
#pragma unroll
        for (int j = 0; j < NDIM / (WN * 8); j++) {
            int col = wn * 64 + j * 8 + (lane & 3) * 2;
            if (row0 < M)
                *(__half2*)&Cout[(size_t)row0 * NDIM + col] =
                    __floats2half2_rn(acc[im][j][0] * d0, acc[im][j][1] * d0);
            if (row1 < M)
                *(__half2*)&Cout[(size_t)row1 * NDIM + col] =
                    __floats2half2_rn(acc[im][j][2] * d1, acc[im][j][3] * d1);
        }
    }
}

// ---------------------------------------------------------------------------
// Gather-reduce aggregation, 128 fp16 channels: one warp per dst node.
// Each lane owns 4 channels (uint2 = 4 halves). 8-deep unroll (16 regs of loads).
__global__ __launch_bounds__(256)
void agg128(const __half* __restrict__ hs, const float* __restrict__ bias,
            float* __restrict__ out, int n) {
    int warp = (blockIdx.x * blockDim.x + threadIdx.x) >> 5;
    int lane = threadIdx.x & 31;
    if (warp >= n) return;
    const int node = warp;

    float4 acc;
    {
        uint2 r = *(const uint2*)&hs[(size_t)node * C1 + lane * 4];
        float2 f0 = __half22float2(*(__half2*)&r.x);
        float2 f1 = __half22float2(*(__half2*)&r.y);
        acc = make_float4(f0.x, f0.y, f1.x, f1.y);
    }
    int e   = g_rowstart[node];
    int cnt = g_deg[node];

    while (cnt > 0) {
        int take = min(cnt, 32);
        int s = 0;
        if (lane < take) s = g_csr[e + lane];
        int k = 0;
        for (; k + 8 <= take; k += 8) {
            uint2 r[8];
#pragma unroll
            for (int q = 0; q < 8; q++) {
                int sq = __shfl_sync(0xffffffffu, s, k + q);
                r[q] = *(const uint2*)&hs[(size_t)sq * C1 + lane * 4];
            }
#pragma unroll
            for (int q = 0; q < 8; q++) {
                float2 f0 = __half22float2(*(__half2*)&r[q].x);
                float2 f1 = __half22float2(*(__half2*)&r[q].y);
                acc.x += f0.x; acc.y += f0.y; acc.z += f1.x; acc.w += f1.y;
            }
        }
        for (; k < take; k++) {
            int sk = __shfl_sync(0xffffffffu, s, k);
            uint2 r = *(const uint2*)&hs[(size_t)sk * C1 + lane * 4];
            float2 f0 = __half22float2(*(__half2*)&r.x);
            float2 f1 = __half22float2(*(__half2*)&r.y);
            acc.x += f0.x; acc.y += f0.y; acc.z += f1.x; acc.w += f1.y;
        }
        e += take; cnt -= take;
    }

    float d   = g_dis[node];
    float4 bb = ((const float4*)bias)[lane];
    float4 r;
    r.x = fmaxf(fmaf(d, acc.x, bb.x), 0.0f);
    r.y = fmaxf(fmaf(d, acc.y, bb.y), 0.0f);
    r.z = fmaxf(fmaf(d, acc.z, bb.z), 0.0f);
    r.w = fmaxf(fmaf(d, acc.w, bb.w), 0.0f);
    *(float4*)&out[(size_t)node * C1 + lane * 4] = r;
}

// 64-ch fp16 aggregation: one warp per node, each lane owns 2 channels (half2).
__global__ __launch_bounds__(256)
void agg64(const __half* __restrict__ hs, const float* __restrict__ bias,
           float* __restrict__ out, int n) {
    int warp = (blockIdx.x * blockDim.x + threadIdx.x) >> 5;
    int lane = threadIdx.x & 31;
    if (warp >= n) return;
    const int node = warp;

    float2 acc;
    {
        uint32_t r = *(const uint32_t*)&hs[(size_t)node * C2 + lane * 2];
        acc = __half22float2(*(__half2*)&r);
    }
    int e   = g_rowstart[node];
    int cnt = g_deg[node];

    while (cnt > 0) {
        int take = min(cnt, 32);
        int s = 0;
        if (lane < take) s = g_csr[e + lane];
        int k = 0;
        for (; k + 8 <= take; k += 8) {
            uint32_t r[8];
#pragma unroll
            for (int q = 0; q < 8; q++) {
                int sq = __shfl_sync(0xffffffffu, s, k + q);
                r[q] = *(const uint32_t*)&hs[(size_t)sq * C2 + lane * 2];
            }
#pragma unroll
            for (int q = 0; q < 8; q++) {
                float2 f = __half22float2(*(__half2*)&r[q]);
                acc.x += f.x; acc.y += f.y;
            }
        }
        for (; k < take; k++) {
            int sk = __shfl_sync(0xffffffffu, s, k);
            uint32_t r = *(const uint32_t*)&hs[(size_t)sk * C2 + lane * 2];
            float2 f = __half22float2(*(__half2*)&r);
            acc.x += f.x; acc.y += f.y;
        }
        e += take; cnt -= take;
    }

    float d   = g_dis[node];
    float2 bb = ((const float2*)bias)[lane];
    float2 r;
    r.x = fmaxf(fmaf(d, acc.x, bb.x), 0.0f);
    r.y = fmaxf(fmaf(d, acc.y, bb.y), 0.0f);
    *(float2*)&out[(size_t)node * C2 + lane * 2] = r;
}

// ---------------------------------------------------------------------------
extern "C" void kernel_launch(void* const* d_in, const int* in_sizes, int n_in,
                              void* d_out, int out_size) {
    const float* x  = (const float*)d_in[0];
    const int*   ei = (const int*)d_in[1];
    const float* W1 = (const float*)d_in[2];
    const float* b1 = (const float*)d_in[3];
    const float* W2 = (const float*)d_in[4];
    const float* b2 = (const float*)d_in[5];
    float* out = (float*)d_out;

    const int E = in_sizes[1] / 2;
    const int N = in_sizes[0] / IN_CH;
    const int* src = ei;
    const int* dst = ei + E;

    __half *hs1, *hs2;
    float *x2;
    uint4 *w1h, *w1l, *w2h, *w2l;
    cudaGetSymbolAddress((void**)&hs1, g_hs1);
    cudaGetSymbolAddress((void**)&x2,  g_x2);
    cudaGetSymbolAddress((void**)&hs2, g_hs2);
    cudaGetSymbolAddress((void**)&w1h, g_W1hi);
    cudaGetSymbolAddress((void**)&w1l, g_W1lo);
    cudaGetSymbolAddress((void**)&w2h, g_W2hi);
    cudaGetSymbolAddress((void**)&w2l, g_W2lo);

    constexpr int SMEM1 = 2 * 128 * 128 + 2 * 128 * 128;  // 65536
    constexpr int SMEM2 = 2 * 256 * 128 + 2 * 64 * 128;   // 81920
    cudaFuncSetAttribute(gemm_mma<128, 128, 256, 4, 2>,
                         cudaFuncAttributeMaxDynamicSharedMemorySize, SMEM1);
    cudaFuncSetAttribute(gemm_mma<256, 64, 128, 8, 1>,
                         cudaFuncAttributeMaxDynamicSharedMemorySize, SMEM2);

    // prep: zero deg + weight images
    {
        int total = (N > IN_CH * C1) ? N : IN_CH * C1;
        prep_kernel<<<(total + 255) / 256, 256>>>(W1, W2, N);
    }
    deg_kernel<<<((E + 3) / 4 + 255) / 256, 256>>>(dst, E);
    int nb = (N + 511) / 512;
    scanA<<<nb, 512>>>(N);
    scanC<<<(N + 255) / 256, 256>>>(N, nb);
    fill_csr<<<((E + 3) / 4 + 255) / 256, 256>>>(src, dst, E);

    // ---- layer 1 ----
    gemm_mma<128, 128, 256, 4, 2><<<(N + 127) / 128, 256, SMEM1>>>(x, w1h, w1l, hs1, N);
    agg128<<<(N * 32 + 255) / 256, 256>>>(hs1, b1, x2, N);

    // ---- layer 2 ----
    gemm_mma<256, 64, 128, 8, 1><<<(N + 255) / 256, 256, SMEM2>>>(x2, w2h, w2l, hs2, N);
    agg64<<<(N * 32 + 255) / 256, 256>>>(hs2, b2, out, N);
}

// round 9
// speedup vs baseline: 1.2293x; 1.1391x over previous
#include <cuda_runtime.h>
#include <cuda_bf16.h>
#include <cuda_fp16.h>
#include <cstdint>

// Problem constants (fixed by the dataset)
#define NN_MAX   50000
#define EDGE_MAX 800000
#define IN_CH    256
#define C1       128
#define C2       64

// -------- scratch (no allocations allowed -> __device__ globals) -----------
__device__ int    g_deg     [NN_MAX];
__device__ int    g_prefix  [NN_MAX];
__device__ int    g_bsum    [256];
__device__ int    g_rowstart[NN_MAX];
__device__ int    g_cursor  [NN_MAX];
__device__ int2   g_csr2    [EDGE_MAX];      // (src, dis[src] bits) grouped by dst
__device__ float  g_dis     [NN_MAX];
__device__ __half g_h1      [NN_MAX * C1];   // x@W1 (raw, fp16)
__device__ float  g_x2      [NN_MAX * C1];   // relu output of layer 1 (fp32)
__device__ __half g_h2      [NN_MAX * C2];   // x2@W2 (raw, fp16)
// Pre-swizzled (SW128) bf16 hi/lo images of W^T, layout [kchunk][n][k64], 128B rows.
__device__ uint4 g_W1hi[4096], g_W1lo[4096];   // 4 chunks x 128n x 128B
__device__ uint4 g_W2hi[1024], g_W2lo[1024];   // 2 chunks x  64n x 128B

#define SW128(o) ((o) ^ (((o) >> 3) & 0x70))

__device__ __forceinline__ uint32_t smem_u32(const void* p) {
    uint32_t a;
    asm("{ .reg .u64 t; cvta.to.shared.u64 t, %1; cvt.u32.u64 %0, t; }" : "=r"(a) : "l"(p));
    return a;
}
__device__ __forceinline__ void ldsm_x4(uint32_t* r, uint32_t addr) {
    asm volatile("ldmatrix.sync.aligned.m8n8.x4.shared.b16 {%0,%1,%2,%3}, [%4];"
                 : "=r"(r[0]), "=r"(r[1]), "=r"(r[2]), "=r"(r[3]) : "r"(addr));
}
__device__ __forceinline__ void mma_bf16(float* d, const uint32_t* a,
                                         uint32_t b0, uint32_t b1) {
    asm volatile(
        "mma.sync.aligned.m16n8k16.row.col.f32.bf16.bf16.f32 "
        "{%0,%1,%2,%3}, {%4,%5,%6,%7}, {%8,%9}, {%0,%1,%2,%3};"
        : "+f"(d[0]), "+f"(d[1]), "+f"(d[2]), "+f"(d[3])
        : "r"(a[0]), "r"(a[1]), "r"(a[2]), "r"(a[3]), "r"(b0), "r"(b1));
}

// ---------------------------------------------------------------------------
// Fused prep: zero g_deg + build swizzled bf16 hi/lo weight images.
__global__ void prep_kernel(const float* __restrict__ W1, const float* __restrict__ W2, int n) {
    int idx = blockIdx.x * blockDim.x + threadIdx.x;
    if (idx < n) g_deg[idx] = 0;
    if (idx < IN_CH * C1) {
        int k = idx / C1, nn = idx % C1;
        float v = W1[k * C1 + nn];
        __nv_bfloat16 h = __float2bfloat16_rn(v);
        __nv_bfloat16 l = __float2bfloat16_rn(v - __bfloat162float(h));
        int c = k >> 6, kk = k & 63;
        int off = c * 16384 + SW128(nn * 128 + kk * 2);
        *(__nv_bfloat16*)((char*)g_W1hi + off) = h;
        *(__nv_bfloat16*)((char*)g_W1lo + off) = l;
        if (idx < C1 * C2) {
            int k2 = idx / C2, n2 = idx % C2;
            float v2 = W2[k2 * C2 + n2];
            __nv_bfloat16 h2 = __float2bfloat16_rn(v2);
            __nv_bfloat16 l2 = __float2bfloat16_rn(v2 - __bfloat162float(h2));
            int c2 = k2 >> 6, kk2 = k2 & 63;
            int off2 = c2 * 8192 + SW128(n2 * 128 + kk2 * 2);
            *(__nv_bfloat16*)((char*)g_W2hi + off2) = h2;
            *(__nv_bfloat16*)((char*)g_W2lo + off2) = l2;
        }
    }
}

// Degree count: 4 edges per thread (int4 load) for MLP.
__global__ void deg_kernel(const int* __restrict__ dst, int E) {
    int base = (blockIdx.x * blockDim.x + threadIdx.x) * 4;
    if (base + 3 < E) {
        int4 d = *(const int4*)&dst[base];
        atomicAdd(&g_deg[d.x], 1);
        atomicAdd(&g_deg[d.y], 1);
        atomicAdd(&g_deg[d.z], 1);
        atomicAdd(&g_deg[d.w], 1);
    } else {
        for (int e = base; e < E; e++) atomicAdd(&g_deg[dst[e]], 1);
    }
}

// Parallel scan phase A: per-block exclusive prefix + block sums.
__global__ __launch_bounds__(512) void scanA(int n) {
    __shared__ int s[512];
    int t = threadIdx.x;
    int i = blockIdx.x * 512 + t;
    int v = (i < n) ? g_deg[i] : 0;
    s[t] = v; __syncthreads();
    for (int off = 1; off < 512; off <<= 1) {
        int u = (t >= off) ? s[t - off] : 0;
        __syncthreads(); s[t] += u; __syncthreads();
    }
    if (i < n) g_prefix[i] = s[t] - v;
    if (t == 511) g_bsum[blockIdx.x] = s[511];
}
// Phase B+C fused: every block redundantly scans the <=256 block sums in smem.
__global__ __launch_bounds__(256) void scanC(int n, int nb) {
    __shared__ int sb_[256];
    int t = threadIdx.x;
    int v = (t < nb) ? g_bsum[t] : 0;
    sb_[t] = v; __syncthreads();
    for (int off = 1; off < 256; off <<= 1) {
        int u = (t >= off) ? sb_[t - off] : 0;
        __syncthreads(); sb_[t] += u; __syncthreads();
    }
    if (t < nb) sb_[t] -= v;
    __syncthreads();
    int i = blockIdx.x * 256 + t;
    if (i >= n) return;
    int base = sb_[i >> 9] + g_prefix[i];
    g_rowstart[i] = base;
    g_cursor[i]   = base;
    g_dis[i]      = rsqrtf((float)g_deg[i] + 1.0f);
}

// CSR fill: packs (src, dis[src]) per edge; 4 edges per thread for MLP.
__global__ void fill_csr(const int* __restrict__ src, const int* __restrict__ dst, int E) {
    int base = (blockIdx.x * blockDim.x + threadIdx.x) * 4;
    if (base + 3 < E) {
        int4 d = *(const int4*)&dst[base];
        int4 s = *(const int4*)&src[base];
        float f0 = g_dis[s.x], f1 = g_dis[s.y], f2 = g_dis[s.z], f3 = g_dis[s.w];
        int p0 = atomicAdd(&g_cursor[d.x], 1);
        int p1 = atomicAdd(&g_cursor[d.y], 1);
        int p2 = atomicAdd(&g_cursor[d.z], 1);
        int p3 = atomicAdd(&g_cursor[d.w], 1);
        g_csr2[p0] = make_int2(s.x, __float_as_int(f0));
        g_csr2[p1] = make_int2(s.y, __float_as_int(f1));
        g_csr2[p2] = make_int2(s.z, __float_as_int(f2));
        g_csr2[p3] = make_int2(s.w, __float_as_int(f3));
    } else {
        for (int e = base; e < E; e++) {
            int s = src[e];
            int p = atomicAdd(&g_cursor[dst[e]], 1);
            g_csr2[p] = make_int2(s, __float_as_int(g_dis[s]));
        }
    }
}

// ---------------------------------------------------------------------------
// Warp-MMA split-bf16 GEMM: h[m][n] = half( sum_k A[m][k] * W[k][n] )  (no dis)
template<int MTILE, int NDIM, int KDIM, int WM, int WN>
__global__ __launch_bounds__(256) void gemm_mma(
    const float* __restrict__ A, const uint4* __restrict__ Bhi,
    const uint4* __restrict__ Blo, __half* __restrict__ Cout, int M)
{
    constexpr int SA_HI = 0;
    constexpr int SA_LO = MTILE * 128;
    constexpr int SB_HI = 2 * MTILE * 128;
    constexpr int SB_LO = SB_HI + NDIM * 128;
    constexpr int NCH   = KDIM / 64;
    constexpr int BNV   = NDIM * 8;

    extern __shared__ char smem[];
    const uint32_t sb = smem_u32(smem);
    const int tid  = threadIdx.x;
    const int wid  = tid >> 5, lane = tid & 31;
    const int wm   = wid / WN, wn = wid % WN;
    const int m0   = blockIdx.x * MTILE;

    const int row_l  = lane & 15;
    const int colsel = (lane >> 4) * 8;

    float acc[2][NDIM / 8][4];
#pragma unroll
    for (int i = 0; i < 2; i++)
#pragma unroll
        for (int j = 0; j < NDIM / 8; j++)
#pragma unroll
            for (int q = 0; q < 4; q++) acc[i][j][q] = 0.0f;

    for (int c = 0; c < NCH; c++) {
        for (int i = tid; i < MTILE * 16; i += 256) {
            int m = i >> 4, kk = (i & 15) * 4;
            int gm = m0 + m;
            float4 v = make_float4(0.f, 0.f, 0.f, 0.f);
            if (gm < M) v = *(const float4*)&A[(size_t)gm * KDIM + c * 64 + kk];
            __nv_bfloat16 h0 = __float2bfloat16_rn(v.x), h1 = __float2bfloat16_rn(v.y);
            __nv_bfloat16 h2 = __float2bfloat16_rn(v.z), h3 = __float2bfloat16_rn(v.w);
            __nv_bfloat16 l0 = __float2bfloat16_rn(v.x - __bfloat162float(h0));
            __nv_bfloat16 l1 = __float2bfloat16_rn(v.y - __bfloat162float(h1));
            __nv_bfloat16 l2 = __float2bfloat16_rn(v.z - __bfloat162float(h2));
            __nv_bfloat16 l3 = __float2bfloat16_rn(v.w - __bfloat162float(h3));
            uint32_t hA = ((uint32_t)__bfloat16_as_ushort(h1) << 16) | __bfloat16_as_ushort(h0);
            uint32_t hB = ((uint32_t)__bfloat16_as_ushort(h3) << 16) | __bfloat16_as_ushort(h2);
            uint32_t lA = ((uint32_t)__bfloat16_as_ushort(l1) << 16) | __bfloat16_as_ushort(l0);
            uint32_t lB = ((uint32_t)__bfloat16_as_ushort(l3) << 16) | __bfloat16_as_ushort(l2);
            int off = SW128(m * 128 + kk * 2);
            *(uint2*)(smem + SA_HI + off) = make_uint2(hA, hB);
            *(uint2*)(smem + SA_LO + off) = make_uint2(lA, lB);
        }
        {
            uint4* bh = (uint4*)(smem + SB_HI);
            uint4* bl = (uint4*)(smem + SB_LO);
            const uint4* gh = Bhi + (size_t)c * BNV;
            const uint4* gl = Blo + (size_t)c * BNV;
            for (int i = tid; i < BNV; i += 256) { bh[i] = gh[i]; bl[i] = gl[i]; }
        }
        __syncthreads();

#pragma unroll
        for (int k16 = 0; k16 < 4; k16++) {
            const int kb = k16 * 16;
            uint32_t ah[2][4], al[2][4];
#pragma unroll
            for (int im = 0; im < 2; im++) {
                int aoff = SW128((wm * 32 + im * 16 + row_l) * 128 + (kb + colsel) * 2);
                ldsm_x4(ah[im], sb + SA_HI + aoff);
                ldsm_x4(al[im], sb + SA_LO + aoff);
            }
#pragma unroll
            for (int j2 = 0; j2 < NDIM / (WN * 16); j2++) {
                int boff = SW128((wn * 64 + j2 * 16 + row_l) * 128 + (kb + colsel) * 2);
                uint32_t bh[4], bl[4];
                ldsm_x4(bh, sb + SB_HI + boff);
                ldsm_x4(bl, sb + SB_LO + boff);
#pragma unroll
                for (int im = 0; im < 2; im++) {
                    float* d0 = acc[im][2 * j2];
                    float* d1 = acc[im][2 * j2 + 1];
                    mma_bf16(d0, ah[im], bh[0], bh[2]);
                    mma_bf16(d0, ah[im], bl[0], bl[2]);
                    mma_bf16(d0, al[im], bh[0], bh[2]);
                    mma_bf16(d1, ah[im], bh[1], bh[3]);
                    mma_bf16(d1, ah[im], bl[1], bl[3]);
                    mma_bf16(d1, al[im], bh[1], bh[3]);
                }
            }
        }
        __syncthreads();
    }

#pragma unroll
    for (int im = 0; im < 2; im++) {
        int row0 = m0 + wm * 32 + im * 16 + (lane >> 2);
        int row1 = row0 + 8;
#pragma unroll
        for (int j = 0; j < NDIM / (WN * 8); j++) {
            int col = wn * 64 + j * 8 + (lane & 3) * 2;
            if (row0 < M)
                *(__half2*)&Cout[(size_t)row0 * NDIM + col] =
                    __floats2half2_rn(acc[im][j][0], acc[im][j][1]);
            if (row1 < M)
                *(__half2*)&Cout[(size_t)row1 * NDIM + col] =
                    __floats2half2_rn(acc[im][j][2], acc[im][j][3]);
        }
    }
}

// ---------------------------------------------------------------------------
// Gather-reduce aggregation, 128 fp16 channels: one warp per dst node.
// acc = h[node]*dis[node] + sum h[src]*dis[src];  out = relu(dis[node]*acc + b)
__global__ __launch_bounds__(256)
void agg128(const __half* __restrict__ hs, const float* __restrict__ bias,
            float* __restrict__ out, int n) {
    int warp = (blockIdx.x * blockDim.x + threadIdx.x) >> 5;
    int lane = threadIdx.x & 31;
    if (warp >= n) return;
    const int node = warp;
    const float dnode = g_dis[node];

    float4 acc;
    {
        uint2 r = *(const uint2*)&hs[(size_t)node * C1 + lane * 4];
        float2 f0 = __half22float2(*(__half2*)&r.x);
        float2 f1 = __half22float2(*(__half2*)&r.y);
        acc = make_float4(f0.x * dnode, f0.y * dnode, f1.x * dnode, f1.y * dnode);
    }
    int e   = g_rowstart[node];
    int cnt = g_deg[node];

    while (cnt > 0) {
        int take = min(cnt, 32);
        int2 sd = make_int2(0, 0);
        if (lane < take) sd = g_csr2[e + lane];
        int k = 0;
        for (; k + 8 <= take; k += 8) {
            uint2 r[8]; float dq[8];
#pragma unroll
            for (int q = 0; q < 8; q++) {
                int sq = __shfl_sync(0xffffffffu, sd.x, k + q);
                dq[q]  = __int_as_float(__shfl_sync(0xffffffffu, sd.y, k + q));
                r[q] = *(const uint2*)&hs[(size_t)sq * C1 + lane * 4];
            }
#pragma unroll
            for (int q = 0; q < 8; q++) {
                float2 f0 = __half22float2(*(__half2*)&r[q].x);
                float2 f1 = __half22float2(*(__half2*)&r[q].y);
                acc.x = fmaf(f0.x, dq[q], acc.x);
                acc.y = fmaf(f0.y, dq[q], acc.y);
                acc.z = fmaf(f1.x, dq[q], acc.z);
                acc.w = fmaf(f1.y, dq[q], acc.w);
            }
        }
        for (; k < take; k++) {
            int sk = __shfl_sync(0xffffffffu, sd.x, k);
            float dk = __int_as_float(__shfl_sync(0xffffffffu, sd.y, k));
            uint2 r = *(const uint2*)&hs[(size_t)sk * C1 + lane * 4];
            float2 f0 = __half22float2(*(__half2*)&r.x);
            float2 f1 = __half22float2(*(__half2*)&r.y);
            acc.x = fmaf(f0.x, dk, acc.x);
            acc.y = fmaf(f0.y, dk, acc.y);
            acc.z = fmaf(f1.x, dk, acc.z);
            acc.w = fmaf(f1.y, dk, acc.w);
        }
        e += take; cnt -= take;
    }

    float4 bb = ((const float4*)bias)[lane];
    float4 r;
    r.x = fmaxf(fmaf(dnode, acc.x, bb.x), 0.0f);
    r.y = fmaxf(fmaf(dnode, acc.y, bb.y), 0.0f);
    r.z = fmaxf(fmaf(dnode, acc.z, bb.z), 0.0f);
    r.w = fmaxf(fmaf(dnode, acc.w, bb.w), 0.0f);
    *(float4*)&out[(size_t)node * C1 + lane * 4] = r;
}

// 64-ch fp16 aggregation: one warp per node, each lane owns 2 channels (half2).
__global__ __launch_bounds__(256)
void agg64(const __half* __restrict__ hs, const float* __restrict__ bias,
           float* __restrict__ out, int n) {
    int warp = (blockIdx.x * blockDim.x + threadIdx.x) >> 5;
    int lane = threadIdx.x & 31;
    if (warp >= n) return;
    const int node = warp;
    const float dnode = g_dis[node];

    float2 acc;
    {
        uint32_t r = *(const uint32_t*)&hs[(size_t)node * C2 + lane * 2];
        float2 f = __half22float2(*(__half2*)&r);
        acc = make_float2(f.x * dnode, f.y * dnode);
    }
    int e   = g_rowstart[node];
    int cnt = g_deg[node];

    while (cnt > 0) {
        int take = min(cnt, 32);
        int2 sd = make_int2(0, 0);
        if (lane < take) sd = g_csr2[e + lane];
        int k = 0;
        for (; k + 8 <= take; k += 8) {
            uint32_t r[8]; float dq[8];
#pragma unroll
            for (int q = 0; q < 8; q++) {
                int sq = __shfl_sync(0xffffffffu, sd.x, k + q);
                dq[q]  = __int_as_float(__shfl_sync(0xffffffffu, sd.y, k + q));
                r[q] = *(const uint32_t*)&hs[(size_t)sq * C2 + lane * 2];
            }
#pragma unroll
            for (int q = 0; q < 8; q++) {
                float2 f = __half22float2(*(__half2*)&r[q]);
                acc.x = fmaf(f.x, dq[q], acc.x);
                acc.y = fmaf(f.y, dq[q], acc.y);
            }
        }
        for (; k < take; k++) {
            int sk = __shfl_sync(0xffffffffu, sd.x, k);
            float dk = __int_as_float(__shfl_sync(0xffffffffu, sd.y, k));
            uint32_t r = *(const uint32_t*)&hs[(size_t)sk * C2 + lane * 2];
            float2 f = __half22float2(*(__half2*)&r);
            acc.x = fmaf(f.x, dk, acc.x);
            acc.y = fmaf(f.y, dk, acc.y);
        }
        e += take; cnt -= take;
    }

    float2 bb = ((const float2*)bias)[lane];
    float2 r;
    r.x = fmaxf(fmaf(dnode, acc.x, bb.x), 0.0f);
    r.y = fmaxf(fmaf(dnode, acc.y, bb.y), 0.0f);
    *(float2*)&out[(size_t)node * C2 + lane * 2] = r;
}

// ---------------------------------------------------------------------------
extern "C" void kernel_launch(void* const* d_in, const int* in_sizes, int n_in,
                              void* d_out, int out_size) {
    const float* x  = (const float*)d_in[0];
    const int*   ei = (const int*)d_in[1];
    const float* W1 = (const float*)d_in[2];
    const float* b1 = (const float*)d_in[3];
    const float* W2 = (const float*)d_in[4];
    const float* b2 = (const float*)d_in[5];
    float* out = (float*)d_out;

    const int E = in_sizes[1] / 2;
    const int N = in_sizes[0] / IN_CH;
    const int* src = ei;
    const int* dst = ei + E;

    __half *h1, *h2;
    float *x2;
    uint4 *w1h, *w1l, *w2h, *w2l;
    cudaGetSymbolAddress((void**)&h1,  g_h1);
    cudaGetSymbolAddress((void**)&x2,  g_x2);
    cudaGetSymbolAddress((void**)&h2,  g_h2);
    cudaGetSymbolAddress((void**)&w1h, g_W1hi);
    cudaGetSymbolAddress((void**)&w1l, g_W1lo);
    cudaGetSymbolAddress((void**)&w2h, g_W2hi);
    cudaGetSymbolAddress((void**)&w2l, g_W2lo);

    constexpr int SMEM1 = 2 * 128 * 128 + 2 * 128 * 128;  // 65536
    constexpr int SMEM2 = 2 * 256 * 128 + 2 * 64 * 128;   // 81920
    cudaFuncSetAttribute(gemm_mma<128, 128, 256, 4, 2>,
                         cudaFuncAttributeMaxDynamicSharedMemorySize, SMEM1);
    cudaFuncSetAttribute(gemm_mma<256, 64, 128, 8, 1>,
                         cudaFuncAttributeMaxDynamicSharedMemorySize, SMEM2);

    // Lazily-created side stream + fork/join events (first call is uncaptured).
    static cudaStream_t s_side = nullptr;
    static cudaEvent_t  ev_fork = nullptr, ev_join = nullptr;
    if (!s_side) {
        cudaStreamCreateWithFlags(&s_side, cudaStreamNonBlocking);
        cudaEventCreateWithFlags(&ev_fork, cudaEventDisableTiming);
        cudaEventCreateWithFlags(&ev_join, cudaEventDisableTiming);
    }

    // prep: zero deg + weight images (needed by both branches)
    {
        int total = (N > IN_CH * C1) ? N : IN_CH * C1;
        prep_kernel<<<(total + 255) / 256, 256>>>(W1, W2, N);
    }

    // Fork: CSR-build chain on side stream, gemm1 on main stream (independent).
    cudaEventRecord(ev_fork, 0);
    cudaStreamWaitEvent(s_side, ev_fork, 0);

    deg_kernel<<<((E + 3) / 4 + 255) / 256, 256, 0, s_side>>>(dst, E);
    int nb = (N + 511) / 512;
    scanA<<<nb, 512, 0, s_side>>>(N);
    scanC<<<(N + 255) / 256, 256, 0, s_side>>>(N, nb);
    fill_csr<<<((E + 3) / 4 + 255) / 256, 256, 0, s_side>>>(src, dst, E);
    cudaEventRecord(ev_join, s_side);

    // ---- layer 1 GEMM (no dis dependency) ----
    gemm_mma<128, 128, 256, 4, 2><<<(N + 127) / 128, 256, SMEM1>>>(x, w1h, w1l, h1, N);

    // Join: aggregation needs both gemm1 (stream order) and the CSR chain.
    cudaStreamWaitEvent(0, ev_join, 0);
    agg128<<<(N * 32 + 255) / 256, 256>>>(h1, b1, x2, N);

    // ---- layer 2 ----
    gemm_mma<256, 64, 128, 8, 1><<<(N + 255) / 256, 256, SMEM2>>>(x2, w2h, w2l, h2, N);
    agg64<<<(N * 32 + 255) / 256, 256>>>(h2, b2, out, N);
}